// round 3
// baseline (speedup 1.0000x reference)
#include <cuda_runtime.h>
#include <cuda_bf16.h>

// Problem constants (fixed by the dataset)
constexpr int NMAX = 150000;
constexpr int EMAX = 2400000;
constexpr int HD   = 32;   // hidden dim == warp size

// ---------------- scratch (device globals; no allocation allowed) ----------
__device__ float g_h[(long long)NMAX * HD];     // layer features (post-GEMM)
__device__ float g_agg[(long long)NMAX * HD];   // layer output (post agg+bias+relu)
__device__ int   g_cnt[NMAX];                   // degree histogram / fill counters
__device__ int   g_row[NMAX + 1];               // CSR row offsets
__device__ int   g_bsum[1024];                  // scan block sums
__device__ float g_dinv[NMAX];                  // 1/sqrt(deg)
__device__ int   g_csrc[EMAX];                  // CSR src ids
__device__ float g_cnorm[EMAX];                 // CSR edge norm
__device__ float g_pool[HD];                    // sum-pool result

// ---------------- setup kernels --------------------------------------------
__global__ void zero_kernel(int n) {
    int i = blockIdx.x * blockDim.x + threadIdx.x;
    if (i < n) g_cnt[i] = 0;
    if (i < HD) g_pool[i] = 0.0f;
}

// edge_index is int32 (JAX x64 disabled): ei[0:E]=src, ei[E:2E]=dst
__global__ void hist_kernel(const int* __restrict__ ei, int E, int n) {
    int e = blockIdx.x * blockDim.x + threadIdx.x;
    if (e >= E) return;
    unsigned d = (unsigned)ei[E + e];
    if (d < (unsigned)n) atomicAdd(&g_cnt[d], 1);
}

// block-local inclusive scan (1024/block) -> g_row[i+1], block totals -> g_bsum
__global__ void scan1_kernel(int n) {
    __shared__ int sh[1024];
    int i = blockIdx.x * 1024 + threadIdx.x;
    sh[threadIdx.x] = (i < n) ? g_cnt[i] : 0;
    __syncthreads();
    for (int off = 1; off < 1024; off <<= 1) {
        int v = (threadIdx.x >= off) ? sh[threadIdx.x - off] : 0;
        __syncthreads();
        sh[threadIdx.x] += v;
        __syncthreads();
    }
    if (i < n) g_row[i + 1] = sh[threadIdx.x];
    if (threadIdx.x == 1023) g_bsum[blockIdx.x] = sh[1023];
}

// exclusive scan of block sums (single block, nb <= 1024)
__global__ void scan2_kernel(int nb) {
    __shared__ int sh[1024];
    sh[threadIdx.x] = (threadIdx.x < nb) ? g_bsum[threadIdx.x] : 0;
    __syncthreads();
    for (int off = 1; off < 1024; off <<= 1) {
        int v = (threadIdx.x >= off) ? sh[threadIdx.x - off] : 0;
        __syncthreads();
        sh[threadIdx.x] += v;
        __syncthreads();
    }
    int excl = (threadIdx.x == 0) ? 0 : sh[threadIdx.x - 1];
    if (threadIdx.x < nb) g_bsum[threadIdx.x] = excl;
}

__global__ void scan3_kernel(int n) {
    int i = blockIdx.x * blockDim.x + threadIdx.x;
    if (i < n) g_row[i + 1] += g_bsum[i >> 10];
    if (i == 0) g_row[0] = 0;
}

// dinv = rsqrt(in_degree + 1 self loop); reset g_cnt for use as fill counters
__global__ void dinv_kernel(int n) {
    int i = blockIdx.x * blockDim.x + threadIdx.x;
    if (i < n) {
        g_dinv[i] = rsqrtf((float)(g_cnt[i] + 1));
        g_cnt[i] = 0;
    }
}

__global__ void scatter_kernel(const int* __restrict__ ei, int E, int n) {
    int e = blockIdx.x * blockDim.x + threadIdx.x;
    if (e >= E) return;
    unsigned s = (unsigned)ei[e];
    unsigned d = (unsigned)ei[E + e];
    if (s >= (unsigned)n || d >= (unsigned)n) return;
    int slot = g_row[d] + atomicAdd(&g_cnt[d], 1);
    g_csrc[slot]  = (int)s;
    g_cnorm[slot] = g_dinv[s] * g_dinv[d];
}

// ---------------- dense feature transform: g_h = in @ W ---------------------
// warp per node; lane = output feature; W staged in shared; row via shfl.
// IN_GLOBAL=false: read from parameter x (layer 1). true: read from g_agg.
template <int FIN, bool IN_GLOBAL>
__global__ void gemm_kernel(const float* __restrict__ x,
                            const float* __restrict__ W, int n) {
    __shared__ float Ws[FIN * HD];
    for (int i = threadIdx.x; i < FIN * HD; i += blockDim.x) Ws[i] = W[i];
    __syncthreads();
    int w    = (blockIdx.x * blockDim.x + threadIdx.x) >> 5;
    int lane = threadIdx.x & 31;
    if (w >= n) return;
    const float* xr = (IN_GLOBAL ? g_agg : x) + (long long)w * FIN;
    float a = (lane < FIN) ? xr[lane] : 0.0f;
    float b = 0.0f;
    if (FIN > 32) b = (lane + 32 < FIN) ? xr[lane + 32] : 0.0f;
    float acc = 0.0f;
#pragma unroll
    for (int k = 0; k < ((FIN < 32) ? FIN : 32); k++)
        acc = fmaf(__shfl_sync(0xffffffffu, a, k), Ws[k * HD + lane], acc);
    if (FIN > 32) {
#pragma unroll
        for (int k = 0; k < FIN - 32; k++)
            acc = fmaf(__shfl_sync(0xffffffffu, b, k), Ws[(32 + k) * HD + lane], acc);
    }
    g_h[(long long)w * HD + lane] = acc;
}

// ---------------- sparse aggregation + bias + relu --------------------------
// warp per dst node; lane = feature. g_agg = relu(sum_e g_h[src_e]*norm_e
//                                               + g_h[dst]*dinv^2 + bias)
__global__ void agg_kernel(const float* __restrict__ bias, int n) {
    int w    = (blockIdx.x * blockDim.x + threadIdx.x) >> 5;
    int lane = threadIdx.x & 31;
    if (w >= n) return;
    float di  = g_dinv[w];
    float acc = g_h[(long long)w * HD + lane] * (di * di);   // self loop
    int s = g_row[w], e = g_row[w + 1];
    int i = s;
    for (; i + 3 < e; i += 4) {
        int   s0 = g_csrc[i],     s1 = g_csrc[i + 1];
        int   s2 = g_csrc[i + 2], s3 = g_csrc[i + 3];
        float n0 = g_cnorm[i],     n1 = g_cnorm[i + 1];
        float n2 = g_cnorm[i + 2], n3 = g_cnorm[i + 3];
        float h0 = g_h[(long long)s0 * HD + lane];
        float h1 = g_h[(long long)s1 * HD + lane];
        float h2 = g_h[(long long)s2 * HD + lane];
        float h3 = g_h[(long long)s3 * HD + lane];
        acc = fmaf(h0, n0, acc);
        acc = fmaf(h1, n1, acc);
        acc = fmaf(h2, n2, acc);
        acc = fmaf(h3, n3, acc);
    }
    for (; i < e; i++)
        acc = fmaf(g_h[(long long)g_csrc[i] * HD + lane], g_cnorm[i], acc);
    g_agg[(long long)w * HD + lane] = fmaxf(acc + bias[lane], 0.0f);
}

// ---------------- sum pool over nodes ---------------------------------------
__global__ void pool_kernel(int n) {
    int lane   = threadIdx.x & 31;
    int warp   = (blockIdx.x * blockDim.x + threadIdx.x) >> 5;
    int nwarps = (gridDim.x * blockDim.x) >> 5;
    float acc = 0.0f;
    for (int v = warp; v < n; v += nwarps)
        acc += g_agg[(long long)v * HD + lane];
    atomicAdd(&g_pool[lane], acc);
}

// ---------------- tiny MLP head ----------------------------------------------
__global__ void mlp_kernel(const float* __restrict__ Wl1, const float* __restrict__ bl1,
                           const float* __restrict__ Wl2, const float* __restrict__ bl2,
                           float* __restrict__ out) {
    __shared__ float z[16];
    int t = threadIdx.x;
    if (t < 16) {
        float s = bl1[t];
#pragma unroll
        for (int k = 0; k < 32; k++) s = fmaf(g_pool[k], Wl1[k * 16 + t], s);
        z[t] = fmaxf(s, 0.0f);
    }
    __syncthreads();
    if (t < 3) {
        float s = bl2[t];
#pragma unroll
        for (int j = 0; j < 16; j++) s = fmaf(z[j], Wl2[j * 3 + t], s);
        out[t] = s;
    }
}

// ---------------- launch ------------------------------------------------------
extern "C" void kernel_launch(void* const* d_in, const int* in_sizes, int n_in,
                              void* d_out, int out_size) {
    const float* x   = (const float*)d_in[0];
    const int*   ei  = (const int*)d_in[1];   // int32! (JAX x64 disabled)
    const float* W1  = (const float*)d_in[2];
    const float* b1  = (const float*)d_in[3];
    const float* W2  = (const float*)d_in[4];
    const float* b2  = (const float*)d_in[5];
    const float* W3  = (const float*)d_in[6];
    const float* b3  = (const float*)d_in[7];
    const float* W4  = (const float*)d_in[8];
    const float* b4  = (const float*)d_in[9];
    const float* Wl1 = (const float*)d_in[10];
    const float* bl1 = (const float*)d_in[11];
    const float* Wl2 = (const float*)d_in[12];
    const float* bl2 = (const float*)d_in[13];
    float*       out = (float*)d_out;

    const int fin = in_sizes[2] / HD;       // 61
    const int n   = in_sizes[0] / fin;      // 150000
    const int e   = in_sizes[1] / 2;        // 2400000

    const int T = 256;
    int nB  = (n + T - 1) / T;
    int eB  = (e + T - 1) / T;
    int wB  = (int)(((long long)n * 32 + T - 1) / T);   // warp-per-node grids
    int sB  = (n + 1023) / 1024;

    // --- graph structure (once per launch) ---
    zero_kernel<<<nB, T>>>(n);
    hist_kernel<<<eB, T>>>(ei, e, n);
    scan1_kernel<<<sB, 1024>>>(n);
    scan2_kernel<<<1, 1024>>>(sB);
    scan3_kernel<<<nB, T>>>(n);
    dinv_kernel<<<nB, T>>>(n);
    scatter_kernel<<<eB, T>>>(ei, e, n);

    // --- layer 1 ---
    gemm_kernel<61, false><<<wB, T>>>(x, W1, n);
    agg_kernel<<<wB, T>>>(b1, n);
    // --- layer 2 ---
    gemm_kernel<32, true><<<wB, T>>>(nullptr, W2, n);
    agg_kernel<<<wB, T>>>(b2, n);
    // --- layer 3 ---
    gemm_kernel<32, true><<<wB, T>>>(nullptr, W3, n);
    agg_kernel<<<wB, T>>>(b3, n);
    // --- layer 4 ---
    gemm_kernel<32, true><<<wB, T>>>(nullptr, W4, n);
    agg_kernel<<<wB, T>>>(b4, n);

    // --- pool + MLP head ---
    pool_kernel<<<512, T>>>(n);
    mlp_kernel<<<1, 32>>>(Wl1, bl1, Wl2, bl2, out);
}

// round 4
// speedup vs baseline: 1.2122x; 1.2122x over previous
#include <cuda_runtime.h>
#include <cuda_fp16.h>

// Problem constants (fixed by the dataset)
constexpr int NMAX = 150000;
constexpr int EMAX = 2400000;
constexpr int HD   = 32;   // hidden dim == warp size

// ---------------- scratch (device globals; no allocation allowed) ----------
__device__ __half g_hA[(long long)NMAX * HD];  // ping feature buffer (h * dinv, fp16)
__device__ __half g_hB[(long long)NMAX * HD];  // pong feature buffer
__device__ int    g_cnt[NMAX];                 // degree histogram / fill counters
__device__ int    g_row[NMAX + 1];             // CSR row offsets
__device__ int    g_bsum[1024];                // scan block sums
__device__ float  g_dinv[NMAX];                // 1/sqrt(deg)
__device__ int    g_csrc[EMAX];                // CSR src ids
__device__ float  g_pool[HD];                  // sum-pool result

// ---------------- setup kernels --------------------------------------------
__global__ void zero_kernel(int n) {
    int i = blockIdx.x * blockDim.x + threadIdx.x;
    if (i < n) g_cnt[i] = 0;
    if (i < HD) g_pool[i] = 0.0f;
}

// edge_index is int32: ei[0:E]=src, ei[E:2E]=dst
__global__ void hist_kernel(const int* __restrict__ ei, int E, int n) {
    int e = blockIdx.x * blockDim.x + threadIdx.x;
    if (e >= E) return;
    unsigned d = (unsigned)ei[E + e];
    if (d < (unsigned)n) atomicAdd(&g_cnt[d], 1);
}

// block-local inclusive scan (1024/block) -> g_row[i+1], block totals -> g_bsum
__global__ void scan1_kernel(int n) {
    __shared__ int sh[1024];
    int i = blockIdx.x * 1024 + threadIdx.x;
    sh[threadIdx.x] = (i < n) ? g_cnt[i] : 0;
    __syncthreads();
    for (int off = 1; off < 1024; off <<= 1) {
        int v = (threadIdx.x >= off) ? sh[threadIdx.x - off] : 0;
        __syncthreads();
        sh[threadIdx.x] += v;
        __syncthreads();
    }
    if (i < n) g_row[i + 1] = sh[threadIdx.x];
    if (threadIdx.x == 1023) g_bsum[blockIdx.x] = sh[1023];
}

// exclusive scan of block sums (single block, nb <= 1024)
__global__ void scan2_kernel(int nb) {
    __shared__ int sh[1024];
    sh[threadIdx.x] = (threadIdx.x < nb) ? g_bsum[threadIdx.x] : 0;
    __syncthreads();
    for (int off = 1; off < 1024; off <<= 1) {
        int v = (threadIdx.x >= off) ? sh[threadIdx.x - off] : 0;
        __syncthreads();
        sh[threadIdx.x] += v;
        __syncthreads();
    }
    int excl = (threadIdx.x == 0) ? 0 : sh[threadIdx.x - 1];
    if (threadIdx.x < nb) g_bsum[threadIdx.x] = excl;
}

__global__ void scan3_kernel(int n) {
    int i = blockIdx.x * blockDim.x + threadIdx.x;
    if (i < n) g_row[i + 1] += g_bsum[i >> 10];
    if (i == 0) g_row[0] = 0;
}

// dinv = rsqrt(in_degree + 1 self loop); reset g_cnt for reuse as fill counters
__global__ void dinv_kernel(int n) {
    int i = blockIdx.x * blockDim.x + threadIdx.x;
    if (i < n) {
        g_dinv[i] = rsqrtf((float)(g_cnt[i] + 1));
        g_cnt[i] = 0;
    }
}

// CSR fill: only src ids (norm is folded into stored features)
__global__ void scatter_kernel(const int* __restrict__ ei, int E, int n) {
    int e = blockIdx.x * blockDim.x + threadIdx.x;
    if (e >= E) return;
    unsigned s = (unsigned)ei[e];
    unsigned d = (unsigned)ei[E + e];
    if (s >= (unsigned)n || d >= (unsigned)n) return;
    int slot = g_row[d] + atomicAdd(&g_cnt[d], 1);
    g_csrc[slot] = (int)s;
}

// ---------------- layer 1 transform: g_hA = (x @ W1) * dinv  (fp16) --------
__global__ void gemm1_kernel(const float* __restrict__ x,
                             const float* __restrict__ W, int n) {
    __shared__ float Ws[61 * HD];
    for (int i = threadIdx.x; i < 61 * HD; i += blockDim.x) Ws[i] = W[i];
    __syncthreads();
    int w    = (blockIdx.x * blockDim.x + threadIdx.x) >> 5;
    int lane = threadIdx.x & 31;
    if (w >= n) return;
    const float* xr = x + w * 61;
    float a = xr[lane];                                  // lanes 0..31 (k 0..31)
    float b = (lane < 29) ? xr[lane + 32] : 0.0f;        // k 32..60
    float acc = 0.0f;
#pragma unroll
    for (int k = 0; k < 32; k++)
        acc = fmaf(__shfl_sync(0xffffffffu, a, k), Ws[k * HD + lane], acc);
#pragma unroll
    for (int k = 0; k < 29; k++)
        acc = fmaf(__shfl_sync(0xffffffffu, b, k), Ws[(32 + k) * HD + lane], acc);
    g_hA[w * HD + lane] = __float2half(acc * g_dinv[w]);
}

// ---------------- fused: aggregate -> bias -> relu -> next GEMM -> *dinv ----
// warp per dst node; lane = feature.
// agg[lane] = dinv[w] * (sum_e hin[src_e][lane] + hin[w][lane])
// r = relu(agg + bias);  hout[w][lane] = (r @ Wn)[lane] * dinv[w]
template <bool IN_A>
__global__ void agg_gemm_kernel(const float* __restrict__ bias,
                                const float* __restrict__ Wn, int n) {
    __shared__ float Ws[HD * HD];
    for (int i = threadIdx.x; i < HD * HD; i += blockDim.x) Ws[i] = Wn[i];
    __syncthreads();
    int w    = (blockIdx.x * blockDim.x + threadIdx.x) >> 5;
    int lane = threadIdx.x & 31;
    if (w >= n) return;
    const __half* __restrict__ hin = IN_A ? g_hA : g_hB;
    __half* __restrict__ hout      = IN_A ? g_hB : g_hA;
    float di  = g_dinv[w];
    float acc = __half2float(hin[w * HD + lane]);        // self loop
    int s = g_row[w], e = g_row[w + 1];
    int i = s;
    for (; i + 3 < e; i += 4) {
        int s0 = g_csrc[i],     s1 = g_csrc[i + 1];
        int s2 = g_csrc[i + 2], s3 = g_csrc[i + 3];
        float h0 = __half2float(hin[s0 * HD + lane]);
        float h1 = __half2float(hin[s1 * HD + lane]);
        float h2 = __half2float(hin[s2 * HD + lane]);
        float h3 = __half2float(hin[s3 * HD + lane]);
        acc += (h0 + h1) + (h2 + h3);
    }
    for (; i < e; i++)
        acc += __half2float(hin[g_csrc[i] * HD + lane]);
    float r = fmaxf(fmaf(acc, di, bias[lane]), 0.0f);
    float o = 0.0f;
#pragma unroll
    for (int k = 0; k < HD; k++)
        o = fmaf(__shfl_sync(0xffffffffu, r, k), Ws[k * HD + lane], o);
    hout[w * HD + lane] = __float2half(o * di);
}

// ---------------- fused final: aggregate -> bias -> relu -> sum pool --------
// 1024 threads/block (32 warps); block reduction then one atomicAdd per lane.
template <bool IN_A>
__global__ void agg_pool_kernel(const float* __restrict__ bias, int n) {
    __shared__ float sh[32 * 33];
    int tid  = threadIdx.x;
    int lane = tid & 31;
    int wid  = tid >> 5;
    int w    = (blockIdx.x * 1024 + tid) >> 5;
    const __half* __restrict__ hin = IN_A ? g_hA : g_hB;
    float r = 0.0f;
    if (w < n) {
        float di  = g_dinv[w];
        float acc = __half2float(hin[w * HD + lane]);    // self loop
        int s = g_row[w], e = g_row[w + 1];
        int i = s;
        for (; i + 3 < e; i += 4) {
            int s0 = g_csrc[i],     s1 = g_csrc[i + 1];
            int s2 = g_csrc[i + 2], s3 = g_csrc[i + 3];
            float h0 = __half2float(hin[s0 * HD + lane]);
            float h1 = __half2float(hin[s1 * HD + lane]);
            float h2 = __half2float(hin[s2 * HD + lane]);
            float h3 = __half2float(hin[s3 * HD + lane]);
            acc += (h0 + h1) + (h2 + h3);
        }
        for (; i < e; i++)
            acc += __half2float(hin[g_csrc[i] * HD + lane]);
        r = fmaxf(fmaf(acc, di, bias[lane]), 0.0f);
    }
    sh[wid * 33 + lane] = r;
    __syncthreads();
    if (wid == 0) {
        float s2 = 0.0f;
#pragma unroll
        for (int j = 0; j < 32; j++) s2 += sh[j * 33 + lane];
        atomicAdd(&g_pool[lane], s2);
    }
}

// ---------------- tiny MLP head ---------------------------------------------
__global__ void mlp_kernel(const float* __restrict__ Wl1, const float* __restrict__ bl1,
                           const float* __restrict__ Wl2, const float* __restrict__ bl2,
                           float* __restrict__ out) {
    __shared__ float z[16];
    int t = threadIdx.x;
    if (t < 16) {
        float s = bl1[t];
#pragma unroll
        for (int k = 0; k < 32; k++) s = fmaf(g_pool[k], Wl1[k * 16 + t], s);
        z[t] = fmaxf(s, 0.0f);
    }
    __syncthreads();
    if (t < 3) {
        float s = bl2[t];
#pragma unroll
        for (int j = 0; j < 16; j++) s = fmaf(z[j], Wl2[j * 3 + t], s);
        out[t] = s;
    }
}

// ---------------- launch -----------------------------------------------------
extern "C" void kernel_launch(void* const* d_in, const int* in_sizes, int n_in,
                              void* d_out, int out_size) {
    const float* x   = (const float*)d_in[0];
    const int*   ei  = (const int*)d_in[1];   // int32 (JAX x64 disabled)
    const float* W1  = (const float*)d_in[2];
    const float* b1  = (const float*)d_in[3];
    const float* W2  = (const float*)d_in[4];
    const float* b2  = (const float*)d_in[5];
    const float* W3  = (const float*)d_in[6];
    const float* b3  = (const float*)d_in[7];
    const float* W4  = (const float*)d_in[8];
    const float* b4  = (const float*)d_in[9];
    const float* Wl1 = (const float*)d_in[10];
    const float* bl1 = (const float*)d_in[11];
    const float* Wl2 = (const float*)d_in[12];
    const float* bl2 = (const float*)d_in[13];
    float*       out = (float*)d_out;

    const int fin = in_sizes[2] / HD;       // 61
    const int n   = in_sizes[0] / fin;      // 150000
    const int e   = in_sizes[1] / 2;        // 2400000

    const int T = 256;
    int nB = (n + T - 1) / T;
    int eB = (e + T - 1) / T;
    int wB = (int)(((long long)n * 32 + T - 1) / T);   // warp-per-node, 256 thr
    int pB = (int)(((long long)n * 32 + 1023) / 1024); // warp-per-node, 1024 thr
    int sB = (n + 1023) / 1024;

    // --- graph structure (once per launch) ---
    zero_kernel<<<nB, T>>>(n);
    hist_kernel<<<eB, T>>>(ei, e, n);
    scan1_kernel<<<sB, 1024>>>(n);
    scan2_kernel<<<1, 1024>>>(sB);
    scan3_kernel<<<nB, T>>>(n);
    dinv_kernel<<<nB, T>>>(n);
    scatter_kernel<<<eB, T>>>(ei, e, n);

    // --- layers (fused agg+gemm; ping-pong A/B) ---
    gemm1_kernel<<<wB, T>>>(x, W1, n);                 // x@W1*dinv -> A
    agg_gemm_kernel<true><<<wB, T>>>(b1, W2, n);       // agg(A)+b1,relu,@W2*dinv -> B
    agg_gemm_kernel<false><<<wB, T>>>(b2, W3, n);      // agg(B)+b2,relu,@W3*dinv -> A
    agg_gemm_kernel<true><<<wB, T>>>(b3, W4, n);       // agg(A)+b3,relu,@W4*dinv -> B
    agg_pool_kernel<false><<<pB, 1024>>>(b4, n);       // agg(B)+b4,relu -> pool

    // --- MLP head ---
    mlp_kernel<<<1, 32>>>(Wl1, bl1, Wl2, bl2, out);
}

// round 5
// speedup vs baseline: 1.4890x; 1.2284x over previous
#include <cuda_runtime.h>
#include <cuda_fp16.h>

// Problem constants (fixed by the dataset)
constexpr int NMAX = 150000;
constexpr int EMAX = 2400000;
constexpr int HD   = 32;   // hidden dim

// ---------------- scratch (device globals; no allocation allowed) ----------
__device__ __half g_hA[(long long)NMAX * HD];  // ping feature buffer (h * dinv, fp16)
__device__ __half g_hB[(long long)NMAX * HD];  // pong feature buffer
__device__ int    g_cnt[NMAX];                 // degree histogram / fill counters
__device__ int    g_row[NMAX + 1];             // CSR row offsets
__device__ int    g_bsum[1024];                // scan block sums
__device__ float  g_dinv[NMAX];                // 1/sqrt(deg)
__device__ int    g_csrc[EMAX];                // CSR src ids
__device__ float  g_pool[HD];                  // sum-pool result

// ---------------- setup kernels --------------------------------------------
__global__ void zero_kernel(int n) {
    int i = blockIdx.x * blockDim.x + threadIdx.x;
    if (i < n) g_cnt[i] = 0;
    if (i < HD) g_pool[i] = 0.0f;
}

// edge_index is int32: ei[0:E]=src, ei[E:2E]=dst
__global__ void hist_kernel(const int* __restrict__ ei, int E, int n) {
    int e = blockIdx.x * blockDim.x + threadIdx.x;
    if (e >= E) return;
    unsigned d = (unsigned)ei[E + e];
    if (d < (unsigned)n) atomicAdd(&g_cnt[d], 1);
}

// block-local inclusive scan (1024/block) -> g_row[i+1], block totals -> g_bsum
__global__ void scan1_kernel(int n) {
    __shared__ int sh[1024];
    int i = blockIdx.x * 1024 + threadIdx.x;
    sh[threadIdx.x] = (i < n) ? g_cnt[i] : 0;
    __syncthreads();
    for (int off = 1; off < 1024; off <<= 1) {
        int v = (threadIdx.x >= off) ? sh[threadIdx.x - off] : 0;
        __syncthreads();
        sh[threadIdx.x] += v;
        __syncthreads();
    }
    if (i < n) g_row[i + 1] = sh[threadIdx.x];
    if (threadIdx.x == 1023) g_bsum[blockIdx.x] = sh[1023];
}

// exclusive scan of block sums (single block, nb <= 1024)
__global__ void scan2_kernel(int nb) {
    __shared__ int sh[1024];
    sh[threadIdx.x] = (threadIdx.x < nb) ? g_bsum[threadIdx.x] : 0;
    __syncthreads();
    for (int off = 1; off < 1024; off <<= 1) {
        int v = (threadIdx.x >= off) ? sh[threadIdx.x - off] : 0;
        __syncthreads();
        sh[threadIdx.x] += v;
        __syncthreads();
    }
    int excl = (threadIdx.x == 0) ? 0 : sh[threadIdx.x - 1];
    if (threadIdx.x < nb) g_bsum[threadIdx.x] = excl;
}

__global__ void scan3_kernel(int n) {
    int i = blockIdx.x * blockDim.x + threadIdx.x;
    if (i < n) g_row[i + 1] += g_bsum[i >> 10];
    if (i == 0) g_row[0] = 0;
}

// dinv = rsqrt(in_degree + 1 self loop); reset g_cnt for reuse as fill counters
__global__ void dinv_kernel(int n) {
    int i = blockIdx.x * blockDim.x + threadIdx.x;
    if (i < n) {
        g_dinv[i] = rsqrtf((float)(g_cnt[i] + 1));
        g_cnt[i] = 0;
    }
}

// CSR fill: only src ids (norm is folded into stored features)
__global__ void scatter_kernel(const int* __restrict__ ei, int E, int n) {
    int e = blockIdx.x * blockDim.x + threadIdx.x;
    if (e >= E) return;
    unsigned s = (unsigned)ei[e];
    unsigned d = (unsigned)ei[E + e];
    if (s >= (unsigned)n || d >= (unsigned)n) return;
    int slot = g_row[d] + atomicAdd(&g_cnt[d], 1);
    g_csrc[slot] = (int)s;
}

// ---------------- layer 1 transform: g_hA = (x @ W1) * dinv  (fp16) --------
// warp per node; lane = output feature (layout matches half2 view node*16+f)
__global__ void gemm1_kernel(const float* __restrict__ x,
                             const float* __restrict__ W, int n) {
    __shared__ float Ws[61 * HD];
    for (int i = threadIdx.x; i < 61 * HD; i += blockDim.x) Ws[i] = W[i];
    __syncthreads();
    int w    = (blockIdx.x * blockDim.x + threadIdx.x) >> 5;
    int lane = threadIdx.x & 31;
    if (w >= n) return;
    const float* xr = x + w * 61;
    float a = xr[lane];                                  // k 0..31
    float b = (lane < 29) ? xr[lane + 32] : 0.0f;        // k 32..60
    float acc = 0.0f;
#pragma unroll
    for (int k = 0; k < 32; k++)
        acc = fmaf(__shfl_sync(0xffffffffu, a, k), Ws[k * HD + lane], acc);
#pragma unroll
    for (int k = 0; k < 29; k++)
        acc = fmaf(__shfl_sync(0xffffffffu, b, k), Ws[(32 + k) * HD + lane], acc);
    g_hA[w * HD + lane] = __float2half(acc * g_dinv[w]);
}

// ---------------- fused: aggregate -> bias -> relu -> next GEMM -> *dinv ----
// TWO nodes per warp: lanes 0-15 = node A, lanes 16-31 = node B.
// Each lane owns feature pair f = lane&15 as __half2 / float2.
// One csrc LDG and one gather LDG serve both nodes -> 1 LDG per edge.
template <bool IN_A>
__global__ void agg_gemm_kernel(const float* __restrict__ bias,
                                const float* __restrict__ Wn, int n) {
    __shared__ float2 Ws2[HD * 16];   // Ws2[k*16+c] = (W[k][2c], W[k][2c+1])
    for (int i = threadIdx.x; i < HD * 16; i += blockDim.x)
        Ws2[i] = ((const float2*)Wn)[i];
    __syncthreads();
    int gw   = (blockIdx.x * blockDim.x + threadIdx.x) >> 5;
    int lane = threadIdx.x & 31;
    int half = lane >> 4;
    int f    = lane & 15;
    int node = gw * 2 + half;
    if (gw * 2 >= n) return;
    bool valid = node < n;
    int nd = valid ? node : n - 1;
    const __half2* __restrict__ hin = (const __half2*)(IN_A ? g_hA : g_hB);
    __half2* __restrict__ hout      = (__half2*)(IN_A ? g_hB : g_hA);
    float di = g_dinv[nd];
    float2 acc = __half22float2(hin[nd * 16 + f]);       // self loop
    float2 acc1 = make_float2(0.0f, 0.0f);
    int s   = g_row[nd];
    int deg = valid ? (g_row[nd + 1] - s) : 0;
    int mmax = max(deg, __shfl_xor_sync(0xffffffffu, deg, 16));
    for (int i = 0; i < mmax; i += 4) {
        float2 v0 = make_float2(0.f, 0.f), v1 = make_float2(0.f, 0.f);
        float2 v2 = make_float2(0.f, 0.f), v3 = make_float2(0.f, 0.f);
        if (i + 0 < deg) v0 = __half22float2(hin[g_csrc[s + i + 0] * 16 + f]);
        if (i + 1 < deg) v1 = __half22float2(hin[g_csrc[s + i + 1] * 16 + f]);
        if (i + 2 < deg) v2 = __half22float2(hin[g_csrc[s + i + 2] * 16 + f]);
        if (i + 3 < deg) v3 = __half22float2(hin[g_csrc[s + i + 3] * 16 + f]);
        acc.x  += v0.x + v1.x;  acc.y  += v0.y + v1.y;
        acc1.x += v2.x + v3.x;  acc1.y += v2.y + v3.y;
    }
    acc.x += acc1.x; acc.y += acc1.y;
    float2 bb = ((const float2*)bias)[f];
    float r0 = fmaxf(fmaf(acc.x, di, bb.x), 0.0f);
    float r1 = fmaxf(fmaf(acc.y, di, bb.y), 0.0f);
    // GEMM: o[2f..2f+1] = sum_k r[k] * W[k][2f..2f+1], r from own half-warp
    float2 o = make_float2(0.0f, 0.0f);
    int base = half << 4;
#pragma unroll
    for (int k = 0; k < 16; k++) {
        float a0 = __shfl_sync(0xffffffffu, r0, base + k);
        float a1 = __shfl_sync(0xffffffffu, r1, base + k);
        float2 w0 = Ws2[(2 * k) * 16 + f];
        float2 w1 = Ws2[(2 * k + 1) * 16 + f];
        o.x = fmaf(a0, w0.x, fmaf(a1, w1.x, o.x));
        o.y = fmaf(a0, w0.y, fmaf(a1, w1.y, o.y));
    }
    if (valid)
        hout[node * 16 + f] = __floats2half2_rn(o.x * di, o.y * di);
}

// ---------------- fused final: aggregate -> bias -> relu -> sum pool --------
// Same 2-node layout; 1024-thread block reduce, then 2 atomics per feature pair.
template <bool IN_A>
__global__ void agg_pool_kernel(const float* __restrict__ bias, int n) {
    __shared__ float2 sh[32 * 32];
    int tid  = threadIdx.x;
    int lane = tid & 31;
    int wid  = tid >> 5;
    int half = lane >> 4;
    int f    = lane & 15;
    int gw   = (blockIdx.x * 1024 + tid) >> 5;
    int node = gw * 2 + half;
    const __half2* __restrict__ hin = (const __half2*)(IN_A ? g_hA : g_hB);
    float r0 = 0.0f, r1 = 0.0f;
    if (node < n) {
        float di = g_dinv[node];
        float2 acc = __half22float2(hin[node * 16 + f]); // self loop
        float2 acc1 = make_float2(0.0f, 0.0f);
        int s   = g_row[node];
        int deg = g_row[node + 1] - s;
        int mmax = max(deg, __shfl_xor_sync(0xffffffffu, deg, 16));
        for (int i = 0; i < mmax; i += 4) {
            float2 v0 = make_float2(0.f, 0.f), v1 = make_float2(0.f, 0.f);
            float2 v2 = make_float2(0.f, 0.f), v3 = make_float2(0.f, 0.f);
            if (i + 0 < deg) v0 = __half22float2(hin[g_csrc[s + i + 0] * 16 + f]);
            if (i + 1 < deg) v1 = __half22float2(hin[g_csrc[s + i + 1] * 16 + f]);
            if (i + 2 < deg) v2 = __half22float2(hin[g_csrc[s + i + 2] * 16 + f]);
            if (i + 3 < deg) v3 = __half22float2(hin[g_csrc[s + i + 3] * 16 + f]);
            acc.x  += v0.x + v1.x;  acc.y  += v0.y + v1.y;
            acc1.x += v2.x + v3.x;  acc1.y += v2.y + v3.y;
        }
        acc.x += acc1.x; acc.y += acc1.y;
        float2 bb = ((const float2*)bias)[f];
        r0 = fmaxf(fmaf(acc.x, di, bb.x), 0.0f);
        r1 = fmaxf(fmaf(acc.y, di, bb.y), 0.0f);
    } else {
        int deg0 = 0;   // keep shfl participation
        (void)__shfl_xor_sync(0xffffffffu, deg0, 16);
    }
    sh[wid * 32 + lane] = make_float2(r0, r1);
    __syncthreads();
    if (wid == 0) {
        float2 s2 = make_float2(0.0f, 0.0f);
#pragma unroll
        for (int j = 0; j < 32; j++) {
            float2 v = sh[j * 32 + lane];
            s2.x += v.x; s2.y += v.y;
        }
        // combine the two half-warp copies of each feature pair
        s2.x += __shfl_xor_sync(0xffffffffu, s2.x, 16);
        s2.y += __shfl_xor_sync(0xffffffffu, s2.y, 16);
        if (lane < 16) {
            atomicAdd(&g_pool[2 * f + 0], s2.x);
            atomicAdd(&g_pool[2 * f + 1], s2.y);
        }
    }
}

// ---------------- tiny MLP head ---------------------------------------------
__global__ void mlp_kernel(const float* __restrict__ Wl1, const float* __restrict__ bl1,
                           const float* __restrict__ Wl2, const float* __restrict__ bl2,
                           float* __restrict__ out) {
    __shared__ float z[16];
    int t = threadIdx.x;
    if (t < 16) {
        float s = bl1[t];
#pragma unroll
        for (int k = 0; k < 32; k++) s = fmaf(g_pool[k], Wl1[k * 16 + t], s);
        z[t] = fmaxf(s, 0.0f);
    }
    __syncthreads();
    if (t < 3) {
        float s = bl2[t];
#pragma unroll
        for (int j = 0; j < 16; j++) s = fmaf(z[j], Wl2[j * 3 + t], s);
        out[t] = s;
    }
}

// ---------------- launch -----------------------------------------------------
extern "C" void kernel_launch(void* const* d_in, const int* in_sizes, int n_in,
                              void* d_out, int out_size) {
    const float* x   = (const float*)d_in[0];
    const int*   ei  = (const int*)d_in[1];   // int32 (JAX x64 disabled)
    const float* W1  = (const float*)d_in[2];
    const float* b1  = (const float*)d_in[3];
    const float* W2  = (const float*)d_in[4];
    const float* b2  = (const float*)d_in[5];
    const float* W3  = (const float*)d_in[6];
    const float* b3  = (const float*)d_in[7];
    const float* W4  = (const float*)d_in[8];
    const float* b4  = (const float*)d_in[9];
    const float* Wl1 = (const float*)d_in[10];
    const float* bl1 = (const float*)d_in[11];
    const float* Wl2 = (const float*)d_in[12];
    const float* bl2 = (const float*)d_in[13];
    float*       out = (float*)d_out;

    const int fin = in_sizes[2] / HD;       // 61
    const int n   = in_sizes[0] / fin;      // 150000
    const int e   = in_sizes[1] / 2;        // 2400000

    const int T = 256;
    int nB = (n + T - 1) / T;
    int eB = (e + T - 1) / T;
    int wB = (int)(((long long)n * 32 + T - 1) / T);      // warp-per-node (gemm1)
    int nwarps2 = (n + 1) / 2;                            // 2 nodes per warp
    int aB = (int)(((long long)nwarps2 * 32 + T - 1) / T);// agg grids, 256 thr
    int pB = (int)(((long long)nwarps2 * 32 + 1023) / 1024); // pool, 1024 thr
    int sB = (n + 1023) / 1024;

    // --- graph structure (once per launch) ---
    zero_kernel<<<nB, T>>>(n);
    hist_kernel<<<eB, T>>>(ei, e, n);
    scan1_kernel<<<sB, 1024>>>(n);
    scan2_kernel<<<1, 1024>>>(sB);
    scan3_kernel<<<nB, T>>>(n);
    dinv_kernel<<<nB, T>>>(n);
    scatter_kernel<<<eB, T>>>(ei, e, n);

    // --- layers (fused agg+gemm; ping-pong A/B) ---
    gemm1_kernel<<<wB, T>>>(x, W1, n);                 // x@W1*dinv -> A
    agg_gemm_kernel<true><<<aB, T>>>(b1, W2, n);       // agg(A)+b1,relu,@W2*dinv -> B
    agg_gemm_kernel<false><<<aB, T>>>(b2, W3, n);      // agg(B)+b2,relu,@W3*dinv -> A
    agg_gemm_kernel<true><<<aB, T>>>(b3, W4, n);       // agg(A)+b3,relu,@W4*dinv -> B
    agg_pool_kernel<false><<<pB, 1024>>>(b4, n);       // agg(B)+b4,relu -> pool

    // --- MLP head ---
    mlp_kernel<<<1, 32>>>(Wl1, bl1, Wl2, bl2, out);
}

// round 6
// speedup vs baseline: 1.7174x; 1.1534x over previous
#include <cuda_runtime.h>
#include <cuda_fp16.h>

// Problem constants (fixed by the dataset)
constexpr int NMAX = 150000;
constexpr int EMAX = 2400000;
constexpr int HD   = 32;   // hidden dim

// ---------------- scratch (device globals; no allocation allowed) ----------
__device__ __half g_hA[(long long)NMAX * HD];  // ping feature buffer (h * dinv, fp16)
__device__ __half g_hB[(long long)NMAX * HD];  // pong feature buffer
__device__ int    g_cnt[NMAX];                 // degree histogram / fill counters
__device__ int    g_row[NMAX + 1];             // CSR row offsets
__device__ int    g_bsum[1024];                // scan block sums
__device__ float  g_dinv[NMAX];                // 1/sqrt(deg)
__device__ int    g_csrc[EMAX];                // CSR src ids
__device__ float  g_pool[HD];                  // sum-pool result

// ---------------- setup kernels --------------------------------------------
__global__ void zero_kernel(int n) {
    int i = blockIdx.x * blockDim.x + threadIdx.x;
    if (i < n) g_cnt[i] = 0;
    if (i < HD) g_pool[i] = 0.0f;
}

// edge_index is int32: ei[0:E]=src, ei[E:2E]=dst
__global__ void hist_kernel(const int* __restrict__ ei, int E, int n) {
    int e = blockIdx.x * blockDim.x + threadIdx.x;
    if (e >= E) return;
    unsigned d = (unsigned)ei[E + e];
    if (d < (unsigned)n) atomicAdd(&g_cnt[d], 1);
}

// block-local inclusive scan (1024/block) -> g_row[i+1], block totals -> g_bsum
__global__ void scan1_kernel(int n) {
    __shared__ int sh[1024];
    int i = blockIdx.x * 1024 + threadIdx.x;
    sh[threadIdx.x] = (i < n) ? g_cnt[i] : 0;
    __syncthreads();
    for (int off = 1; off < 1024; off <<= 1) {
        int v = (threadIdx.x >= off) ? sh[threadIdx.x - off] : 0;
        __syncthreads();
        sh[threadIdx.x] += v;
        __syncthreads();
    }
    if (i < n) g_row[i + 1] = sh[threadIdx.x];
    if (threadIdx.x == 1023) g_bsum[blockIdx.x] = sh[1023];
}

// exclusive scan of block sums (single block, nb <= 1024)
__global__ void scan2_kernel(int nb) {
    __shared__ int sh[1024];
    sh[threadIdx.x] = (threadIdx.x < nb) ? g_bsum[threadIdx.x] : 0;
    __syncthreads();
    for (int off = 1; off < 1024; off <<= 1) {
        int v = (threadIdx.x >= off) ? sh[threadIdx.x - off] : 0;
        __syncthreads();
        sh[threadIdx.x] += v;
        __syncthreads();
    }
    int excl = (threadIdx.x == 0) ? 0 : sh[threadIdx.x - 1];
    if (threadIdx.x < nb) g_bsum[threadIdx.x] = excl;
}

__global__ void scan3_kernel(int n) {
    int i = blockIdx.x * blockDim.x + threadIdx.x;
    if (i < n) g_row[i + 1] += g_bsum[i >> 10];
    if (i == 0) g_row[0] = 0;
}

// dinv = rsqrt(in_degree + 1 self loop); reset g_cnt for reuse as fill counters
__global__ void dinv_kernel(int n) {
    int i = blockIdx.x * blockDim.x + threadIdx.x;
    if (i < n) {
        g_dinv[i] = rsqrtf((float)(g_cnt[i] + 1));
        g_cnt[i] = 0;
    }
}

// CSR fill: only src ids (norm is folded into stored features)
__global__ void scatter_kernel(const int* __restrict__ ei, int E, int n) {
    int e = blockIdx.x * blockDim.x + threadIdx.x;
    if (e >= E) return;
    unsigned s = (unsigned)ei[e];
    unsigned d = (unsigned)ei[E + e];
    if (s >= (unsigned)n || d >= (unsigned)n) return;
    int slot = g_row[d] + atomicAdd(&g_cnt[d], 1);
    g_csrc[slot] = (int)s;
}

// ---------------- layer 1 transform: g_hA = (x @ W1) * dinv  (fp16) --------
// warp per node; lane = output feature
__global__ void gemm1_kernel(const float* __restrict__ x,
                             const float* __restrict__ W, int n) {
    __shared__ float Ws[61 * HD];
    for (int i = threadIdx.x; i < 61 * HD; i += blockDim.x) Ws[i] = W[i];
    __syncthreads();
    int w    = (blockIdx.x * blockDim.x + threadIdx.x) >> 5;
    int lane = threadIdx.x & 31;
    if (w >= n) return;
    const float* xr = x + w * 61;
    float a = xr[lane];                                  // k 0..31
    float b = (lane < 29) ? xr[lane + 32] : 0.0f;        // k 32..60
    float acc = 0.0f;
#pragma unroll
    for (int k = 0; k < 32; k++)
        acc = fmaf(__shfl_sync(0xffffffffu, a, k), Ws[k * HD + lane], acc);
#pragma unroll
    for (int k = 0; k < 29; k++)
        acc = fmaf(__shfl_sync(0xffffffffu, b, k), Ws[(32 + k) * HD + lane], acc);
    g_hA[w * HD + lane] = __float2half(acc * g_dinv[w]);
}

// ---------------- helpers for 8-node agg layout -----------------------------
// int4 = 8 fp16 features. acc[8] fp32.
__device__ __forceinline__ void acc_add8(float* acc, int4 v) {
    const __half2* h = (const __half2*)&v;
    float2 f0 = __half22float2(h[0]);
    float2 f1 = __half22float2(h[1]);
    float2 f2 = __half22float2(h[2]);
    float2 f3 = __half22float2(h[3]);
    acc[0] += f0.x; acc[1] += f0.y;
    acc[2] += f1.x; acc[3] += f1.y;
    acc[4] += f2.x; acc[5] += f2.y;
    acc[6] += f3.x; acc[7] += f3.y;
}

// ---------------- fused: aggregate -> bias -> relu -> next GEMM -> *dinv ----
// EIGHT nodes per warp: group g = lane>>2 (node slot), chunk c = lane&3.
// Lane owns 8 features [c*8 .. c*8+7] as one int4 (16B) per gather.
// One gather LDG.128 serves 8 edges; csrc coalesced+shfl'd (1 LDG / 32 edges).
template <bool IN_A>
__global__ void agg_gemm_kernel(const float* __restrict__ bias,
                                const float* __restrict__ Wn, int n) {
    __shared__ float4 Ws4[HD * 8];   // Ws4[k*8 + c*2 + h] = W[k][c*8+4h .. +3]
    for (int i = threadIdx.x; i < HD * 8; i += blockDim.x)
        Ws4[i] = ((const float4*)Wn)[i];
    __syncthreads();
    int warp = (blockIdx.x * blockDim.x + threadIdx.x) >> 5;
    int lane = threadIdx.x & 31;
    int g    = lane >> 2;
    int c    = lane & 3;
    int node = warp * 8 + g;
    if (warp * 8 >= n) return;
    bool valid = node < n;
    int nd = valid ? node : n - 1;
    const int4* __restrict__ hin4 = (const int4*)(IN_A ? g_hA : g_hB);
    int4* __restrict__ hout4      = (int4*)(IN_A ? g_hB : g_hA);
    float di = g_dinv[nd];
    float acc[8] = {0, 0, 0, 0, 0, 0, 0, 0};
    acc_add8(acc, hin4[nd * 4 + c]);                     // self loop
    int s   = g_row[nd];
    int deg = valid ? (g_row[nd + 1] - s) : 0;
    int mmax = deg;
    mmax = max(mmax, __shfl_xor_sync(0xffffffffu, mmax, 4));
    mmax = max(mmax, __shfl_xor_sync(0xffffffffu, mmax, 8));
    mmax = max(mmax, __shfl_xor_sync(0xffffffffu, mmax, 16));
    for (int i = 0; i < mmax; i += 4) {
        int cs = (i + c < deg) ? g_csrc[s + i + c] : 0;
#pragma unroll
        for (int j = 0; j < 4; j++) {
            int srcj = __shfl_sync(0xffffffffu, cs, (g << 2) | j);
            if (i + j < deg)
                acc_add8(acc, hin4[srcj * 4 + c]);
        }
    }
    float4 b0 = ((const float4*)bias)[c * 2];
    float4 b1 = ((const float4*)bias)[c * 2 + 1];
    float r[8];
    r[0] = fmaxf(fmaf(acc[0], di, b0.x), 0.0f);
    r[1] = fmaxf(fmaf(acc[1], di, b0.y), 0.0f);
    r[2] = fmaxf(fmaf(acc[2], di, b0.z), 0.0f);
    r[3] = fmaxf(fmaf(acc[3], di, b0.w), 0.0f);
    r[4] = fmaxf(fmaf(acc[4], di, b1.x), 0.0f);
    r[5] = fmaxf(fmaf(acc[5], di, b1.y), 0.0f);
    r[6] = fmaxf(fmaf(acc[6], di, b1.z), 0.0f);
    r[7] = fmaxf(fmaf(acc[7], di, b1.w), 0.0f);
    // GEMM: o[j] = sum_k r_node[k] * W[k][j], j = c*8..c*8+7
    float o[8] = {0, 0, 0, 0, 0, 0, 0, 0};
#pragma unroll
    for (int sc = 0; sc < 4; sc++) {
#pragma unroll
        for (int kk = 0; kk < 8; kk++) {
            float a = __shfl_sync(0xffffffffu, r[kk], (g << 2) | sc);
            int k = sc * 8 + kk;
            float4 w0 = Ws4[k * 8 + c * 2];
            float4 w1 = Ws4[k * 8 + c * 2 + 1];
            o[0] = fmaf(a, w0.x, o[0]); o[1] = fmaf(a, w0.y, o[1]);
            o[2] = fmaf(a, w0.z, o[2]); o[3] = fmaf(a, w0.w, o[3]);
            o[4] = fmaf(a, w1.x, o[4]); o[5] = fmaf(a, w1.y, o[5]);
            o[6] = fmaf(a, w1.z, o[6]); o[7] = fmaf(a, w1.w, o[7]);
        }
    }
    if (valid) {
        int4 pv;
        __half2* ph = (__half2*)&pv;
        ph[0] = __floats2half2_rn(o[0] * di, o[1] * di);
        ph[1] = __floats2half2_rn(o[2] * di, o[3] * di);
        ph[2] = __floats2half2_rn(o[4] * di, o[5] * di);
        ph[3] = __floats2half2_rn(o[6] * di, o[7] * di);
        hout4[node * 4 + c] = pv;
    }
}

// ---------------- fused final: aggregate -> bias -> relu -> sum pool --------
// Same 8-node layout; warp reduce across groups, block reduce, 32 atomics/block.
template <bool IN_A>
__global__ void agg_pool_kernel(const float* __restrict__ bias, int n) {
    __shared__ float sh[32 * 32];
    int tid  = threadIdx.x;
    int lane = tid & 31;
    int wid  = tid >> 5;
    int g    = lane >> 2;
    int c    = lane & 3;
    int warp = (blockIdx.x * 1024 + tid) >> 5;
    int node = warp * 8 + g;
    bool valid = node < n;
    int nd = valid ? node : n - 1;
    const int4* __restrict__ hin4 = (const int4*)(IN_A ? g_hA : g_hB);
    float di = g_dinv[nd];
    float acc[8] = {0, 0, 0, 0, 0, 0, 0, 0};
    acc_add8(acc, hin4[nd * 4 + c]);                     // self loop
    int s   = g_row[nd];
    int deg = valid ? (g_row[nd + 1] - s) : 0;
    int mmax = deg;
    mmax = max(mmax, __shfl_xor_sync(0xffffffffu, mmax, 4));
    mmax = max(mmax, __shfl_xor_sync(0xffffffffu, mmax, 8));
    mmax = max(mmax, __shfl_xor_sync(0xffffffffu, mmax, 16));
    for (int i = 0; i < mmax; i += 4) {
        int cs = (i + c < deg) ? g_csrc[s + i + c] : 0;
#pragma unroll
        for (int j = 0; j < 4; j++) {
            int srcj = __shfl_sync(0xffffffffu, cs, (g << 2) | j);
            if (i + j < deg)
                acc_add8(acc, hin4[srcj * 4 + c]);
        }
    }
    float4 b0 = ((const float4*)bias)[c * 2];
    float4 b1 = ((const float4*)bias)[c * 2 + 1];
    float r[8];
    r[0] = fmaxf(fmaf(acc[0], di, b0.x), 0.0f);
    r[1] = fmaxf(fmaf(acc[1], di, b0.y), 0.0f);
    r[2] = fmaxf(fmaf(acc[2], di, b0.z), 0.0f);
    r[3] = fmaxf(fmaf(acc[3], di, b0.w), 0.0f);
    r[4] = fmaxf(fmaf(acc[4], di, b1.x), 0.0f);
    r[5] = fmaxf(fmaf(acc[5], di, b1.y), 0.0f);
    r[6] = fmaxf(fmaf(acc[6], di, b1.z), 0.0f);
    r[7] = fmaxf(fmaf(acc[7], di, b1.w), 0.0f);
    if (!valid) {
#pragma unroll
        for (int kk = 0; kk < 8; kk++) r[kk] = 0.0f;
    }
    // reduce across the 8 node groups (lanes differing in bits 2,3,4)
#pragma unroll
    for (int kk = 0; kk < 8; kk++) {
        r[kk] += __shfl_xor_sync(0xffffffffu, r[kk], 4);
        r[kk] += __shfl_xor_sync(0xffffffffu, r[kk], 8);
        r[kk] += __shfl_xor_sync(0xffffffffu, r[kk], 16);
    }
    if (lane < 4) {
#pragma unroll
        for (int kk = 0; kk < 8; kk++)
            sh[wid * 32 + c * 8 + kk] = r[kk];
    }
    __syncthreads();
    if (wid == 0) {
        float s2 = 0.0f;
#pragma unroll
        for (int j = 0; j < 32; j++) s2 += sh[j * 32 + lane];
        atomicAdd(&g_pool[lane], s2);
    }
}

// ---------------- tiny MLP head ---------------------------------------------
__global__ void mlp_kernel(const float* __restrict__ Wl1, const float* __restrict__ bl1,
                           const float* __restrict__ Wl2, const float* __restrict__ bl2,
                           float* __restrict__ out) {
    __shared__ float z[16];
    int t = threadIdx.x;
    if (t < 16) {
        float s = bl1[t];
#pragma unroll
        for (int k = 0; k < 32; k++) s = fmaf(g_pool[k], Wl1[k * 16 + t], s);
        z[t] = fmaxf(s, 0.0f);
    }
    __syncthreads();
    if (t < 3) {
        float s = bl2[t];
#pragma unroll
        for (int j = 0; j < 16; j++) s = fmaf(z[j], Wl2[j * 3 + t], s);
        out[t] = s;
    }
}

// ---------------- launch -----------------------------------------------------
extern "C" void kernel_launch(void* const* d_in, const int* in_sizes, int n_in,
                              void* d_out, int out_size) {
    const float* x   = (const float*)d_in[0];
    const int*   ei  = (const int*)d_in[1];   // int32 (JAX x64 disabled)
    const float* W1  = (const float*)d_in[2];
    const float* b1  = (const float*)d_in[3];
    const float* W2  = (const float*)d_in[4];
    const float* b2  = (const float*)d_in[5];
    const float* W3  = (const float*)d_in[6];
    const float* b3  = (const float*)d_in[7];
    const float* W4  = (const float*)d_in[8];
    const float* b4  = (const float*)d_in[9];
    const float* Wl1 = (const float*)d_in[10];
    const float* bl1 = (const float*)d_in[11];
    const float* Wl2 = (const float*)d_in[12];
    const float* bl2 = (const float*)d_in[13];
    float*       out = (float*)d_out;

    const int fin = in_sizes[2] / HD;       // 61
    const int n   = in_sizes[0] / fin;      // 150000
    const int e   = in_sizes[1] / 2;        // 2400000

    const int T = 256;
    int nB = (n + T - 1) / T;
    int eB = (e + T - 1) / T;
    int wB = (int)(((long long)n * 32 + T - 1) / T);      // warp-per-node (gemm1)
    int nwarps8 = (n + 7) / 8;                            // 8 nodes per warp
    int aB = (int)(((long long)nwarps8 * 32 + T - 1) / T);
    int pB = (int)(((long long)nwarps8 * 32 + 1023) / 1024);
    int sB = (n + 1023) / 1024;

    // --- graph structure (once per launch) ---
    zero_kernel<<<nB, T>>>(n);
    hist_kernel<<<eB, T>>>(ei, e, n);
    scan1_kernel<<<sB, 1024>>>(n);
    scan2_kernel<<<1, 1024>>>(sB);
    scan3_kernel<<<nB, T>>>(n);
    dinv_kernel<<<nB, T>>>(n);
    scatter_kernel<<<eB, T>>>(ei, e, n);

    // --- layers (fused agg+gemm; ping-pong A/B) ---
    gemm1_kernel<<<wB, T>>>(x, W1, n);                 // x@W1*dinv -> A
    agg_gemm_kernel<true><<<aB, T>>>(b1, W2, n);       // agg(A)+b1,relu,@W2*dinv -> B
    agg_gemm_kernel<false><<<aB, T>>>(b2, W3, n);      // agg(B)+b2,relu,@W3*dinv -> A
    agg_gemm_kernel<true><<<aB, T>>>(b3, W4, n);       // agg(A)+b3,relu,@W4*dinv -> B
    agg_pool_kernel<false><<<pB, 1024>>>(b4, n);       // agg(B)+b4,relu -> pool

    // --- MLP head ---
    mlp_kernel<<<1, 32>>>(Wl1, bl1, Wl2, bl2, out);
}

// round 7
// speedup vs baseline: 1.9908x; 1.1592x over previous
#include <cuda_runtime.h>
#include <cuda_fp16.h>

// Problem constants (fixed by the dataset)
constexpr int NMAX = 150000;
constexpr int EMAX = 2400000;
constexpr int HD   = 32;   // hidden dim

// ---------------- scratch (device globals; no allocation allowed) ----------
__device__ __half g_hA[(long long)NMAX * HD];  // ping feature buffer (h * dinv, fp16)
__device__ __half g_hB[(long long)NMAX * HD];  // pong feature buffer
__device__ int    g_cnt[NMAX];                 // degree histogram / fill counters
__device__ int    g_row[NMAX + 1];             // CSR row offsets
__device__ int    g_bsum[1024];                // scan block sums
__device__ float  g_dinv[NMAX];                // 1/sqrt(deg)
__device__ int    g_csrc[EMAX];                // CSR src ids
__device__ float  g_pool[HD];                  // sum-pool result

// ---------------- f32x2 packed math helpers ---------------------------------
__device__ __forceinline__ unsigned long long pack2(float x, float y) {
    unsigned long long r;
    asm("mov.b64 %0, {%1, %2};" : "=l"(r) : "f"(x), "f"(y));
    return r;
}
__device__ __forceinline__ void unpack2(unsigned long long v, float& x, float& y) {
    asm("mov.b64 {%0, %1}, %2;" : "=f"(x), "=f"(y) : "l"(v));
}
__device__ __forceinline__ unsigned long long fma2_(unsigned long long a,
                                                    unsigned long long b,
                                                    unsigned long long c) {
    unsigned long long d;
    asm("fma.rn.f32x2 %0, %1, %2, %3;" : "=l"(d) : "l"(a), "l"(b), "l"(c));
    return d;
}

// ---------------- setup kernels --------------------------------------------
__global__ void zero_kernel(int n) {
    int i = blockIdx.x * blockDim.x + threadIdx.x;
    if (i < n) g_cnt[i] = 0;
    if (i < HD) g_pool[i] = 0.0f;
}

// edge_index is int32: ei[0:E]=src, ei[E:2E]=dst
__global__ void hist_kernel(const int* __restrict__ ei, int E, int n) {
    int e = blockIdx.x * blockDim.x + threadIdx.x;
    if (e >= E) return;
    unsigned d = (unsigned)ei[E + e];
    if (d < (unsigned)n) atomicAdd(&g_cnt[d], 1);
}

// block-local inclusive scan (1024/block) -> g_row[i+1], block totals -> g_bsum
__global__ void scan1_kernel(int n) {
    __shared__ int sh[1024];
    int i = blockIdx.x * 1024 + threadIdx.x;
    sh[threadIdx.x] = (i < n) ? g_cnt[i] : 0;
    __syncthreads();
    for (int off = 1; off < 1024; off <<= 1) {
        int v = (threadIdx.x >= off) ? sh[threadIdx.x - off] : 0;
        __syncthreads();
        sh[threadIdx.x] += v;
        __syncthreads();
    }
    if (i < n) g_row[i + 1] = sh[threadIdx.x];
    if (threadIdx.x == 1023) g_bsum[blockIdx.x] = sh[1023];
}

// exclusive scan of block sums: single warp, shfl-based (nb <= 256)
__global__ void scan2_kernel(int nb) {
    int lane = threadIdx.x;
    const int PER = 8;
    int base = lane * PER;
    int v[PER];
    int sum = 0;
#pragma unroll
    for (int j = 0; j < PER; j++) {
        int t = (base + j < nb) ? g_bsum[base + j] : 0;
        v[j] = sum; sum += t;
    }
    int x = sum;
#pragma unroll
    for (int off = 1; off < 32; off <<= 1) {
        int y = __shfl_up_sync(0xffffffffu, x, off);
        if (lane >= off) x += y;
    }
    int excl = x - sum;
#pragma unroll
    for (int j = 0; j < PER; j++)
        if (base + j < nb) g_bsum[base + j] = excl + v[j];
}

// finalize row offsets + dinv + reset counters (fused)
__global__ void scan3_dinv_kernel(int n) {
    int i = blockIdx.x * blockDim.x + threadIdx.x;
    if (i < n) {
        g_row[i + 1] += g_bsum[i >> 10];
        g_dinv[i] = rsqrtf((float)(g_cnt[i] + 1));
        g_cnt[i] = 0;
    }
    if (i == 0) g_row[0] = 0;
}

// CSR fill: only src ids (norm is folded into stored features)
__global__ void scatter_kernel(const int* __restrict__ ei, int E, int n) {
    int e = blockIdx.x * blockDim.x + threadIdx.x;
    if (e >= E) return;
    unsigned s = (unsigned)ei[e];
    unsigned d = (unsigned)ei[E + e];
    if (s >= (unsigned)n || d >= (unsigned)n) return;
    int slot = g_row[d] + atomicAdd(&g_cnt[d], 1);
    g_csrc[slot] = (int)s;
}

// ---------------- layer 1: g_hA = (x @ W1) * dinv, fp16 out -----------------
// FOUR nodes per warp: g = lane>>3, fl = lane&7. Lane owns outputs 4fl..4fl+3
// (two f32x2 accumulators). Activations via shfl, weights via LDS.128 (f32x2).
__global__ void gemm1_kernel(const float* __restrict__ x,
                             const float* __restrict__ W, int n) {
    __shared__ ulonglong2 Wq[61 * 8];   // Wq[k*8+q] = W[k][4q..4q+3] as 2xf32x2
    for (int i = threadIdx.x; i < 61 * 8; i += blockDim.x) {
        float4 f = ((const float4*)W)[i];
        ulonglong2 u;
        u.x = pack2(f.x, f.y);
        u.y = pack2(f.z, f.w);
        Wq[i] = u;
    }
    __syncthreads();
    int warp = (blockIdx.x * blockDim.x + threadIdx.x) >> 5;
    int lane = threadIdx.x & 31;
    int g    = lane >> 3;
    int fl   = lane & 7;
    int node = warp * 4 + g;
    if (warp * 4 >= n) return;
    bool valid = node < n;
    int nd = valid ? node : n - 1;
    // load x row: lane fl owns x[fl*8 .. fl*8+7] of its node
    const float* xr = x + (long long)nd * 61;
    float xa[8];
#pragma unroll
    for (int j = 0; j < 8; j++) {
        int idx = fl * 8 + j;
        xa[j] = (idx < 61) ? xr[idx] : 0.0f;
    }
    unsigned long long o0 = 0ULL, o1 = 0ULL;
#pragma unroll
    for (int k = 0; k < 61; k++) {
        float a = __shfl_sync(0xffffffffu, xa[k & 7], (g << 3) | (k >> 3));
        unsigned long long a2 = pack2(a, a);
        ulonglong2 w = Wq[k * 8 + fl];
        o0 = fma2_(a2, w.x, o0);
        o1 = fma2_(a2, w.y, o1);
    }
    if (valid) {
        float di = g_dinv[node];
        float v0, v1, v2, v3;
        unpack2(o0, v0, v1);
        unpack2(o1, v2, v3);
        __half2 h0 = __floats2half2_rn(v0 * di, v1 * di);
        __half2 h1 = __floats2half2_rn(v2 * di, v3 * di);
        uint2 pv;
        pv.x = *(unsigned*)&h0;
        pv.y = *(unsigned*)&h1;
        *(uint2*)&g_hA[node * HD + 4 * fl] = pv;
    }
}

// ---------------- helpers for 8-node agg layout -----------------------------
// int4 = 8 fp16 features. acc[8] fp32.
__device__ __forceinline__ void acc_add8(float* acc, int4 v) {
    const __half2* h = (const __half2*)&v;
    float2 f0 = __half22float2(h[0]);
    float2 f1 = __half22float2(h[1]);
    float2 f2 = __half22float2(h[2]);
    float2 f3 = __half22float2(h[3]);
    acc[0] += f0.x; acc[1] += f0.y;
    acc[2] += f1.x; acc[3] += f1.y;
    acc[4] += f2.x; acc[5] += f2.y;
    acc[6] += f3.x; acc[7] += f3.y;
}

// ---------------- fused: aggregate -> bias -> relu -> next GEMM -> *dinv ----
// EIGHT nodes per warp: group g = lane>>2, chunk c = lane&3.
// Lane owns 8 features [c*8 .. c*8+7]. One gather LDG.128 serves 8 edges.
// csrc prefetched one iteration ahead to hide L2 latency.
template <bool IN_A>
__global__ void agg_gemm_kernel(const float* __restrict__ bias,
                                const float* __restrict__ Wn, int n) {
    __shared__ ulonglong2 Wq[HD * 8];   // Wq[k*8+q] = W[k][4q..4q+3] as 2xf32x2
    for (int i = threadIdx.x; i < HD * 8; i += blockDim.x) {
        float4 f = ((const float4*)Wn)[i];
        ulonglong2 u;
        u.x = pack2(f.x, f.y);
        u.y = pack2(f.z, f.w);
        Wq[i] = u;
    }
    __syncthreads();
    int warp = (blockIdx.x * blockDim.x + threadIdx.x) >> 5;
    int lane = threadIdx.x & 31;
    int g    = lane >> 2;
    int c    = lane & 3;
    int node = warp * 8 + g;
    if (warp * 8 >= n) return;
    bool valid = node < n;
    int nd = valid ? node : n - 1;
    const int4* __restrict__ hin4 = (const int4*)(IN_A ? g_hA : g_hB);
    int4* __restrict__ hout4      = (int4*)(IN_A ? g_hB : g_hA);
    float di = g_dinv[nd];
    float acc[8] = {0, 0, 0, 0, 0, 0, 0, 0};
    acc_add8(acc, hin4[nd * 4 + c]);                     // self loop
    int s   = g_row[nd];
    int deg = valid ? (g_row[nd + 1] - s) : 0;
    int mmax = deg;
    mmax = max(mmax, __shfl_xor_sync(0xffffffffu, mmax, 4));
    mmax = max(mmax, __shfl_xor_sync(0xffffffffu, mmax, 8));
    mmax = max(mmax, __shfl_xor_sync(0xffffffffu, mmax, 16));
    int cs = (c < deg) ? g_csrc[s + c] : 0;              // prefetch i=0
    for (int i = 0; i < mmax; i += 4) {
        int csn = (i + 4 + c < deg) ? g_csrc[s + i + 4 + c] : 0;  // prefetch next
#pragma unroll
        for (int j = 0; j < 4; j++) {
            int srcj = __shfl_sync(0xffffffffu, cs, (g << 2) | j);
            if (i + j < deg)
                acc_add8(acc, hin4[srcj * 4 + c]);
        }
        cs = csn;
    }
    float4 b0 = ((const float4*)bias)[c * 2];
    float4 b1 = ((const float4*)bias)[c * 2 + 1];
    float r[8];
    r[0] = fmaxf(fmaf(acc[0], di, b0.x), 0.0f);
    r[1] = fmaxf(fmaf(acc[1], di, b0.y), 0.0f);
    r[2] = fmaxf(fmaf(acc[2], di, b0.z), 0.0f);
    r[3] = fmaxf(fmaf(acc[3], di, b0.w), 0.0f);
    r[4] = fmaxf(fmaf(acc[4], di, b1.x), 0.0f);
    r[5] = fmaxf(fmaf(acc[5], di, b1.y), 0.0f);
    r[6] = fmaxf(fmaf(acc[6], di, b1.z), 0.0f);
    r[7] = fmaxf(fmaf(acc[7], di, b1.w), 0.0f);
    // GEMM epilogue (f32x2): o[c*8+q] = sum_k r_node[k] * W[k][c*8+q]
    unsigned long long o2[4] = {0ULL, 0ULL, 0ULL, 0ULL};
#pragma unroll
    for (int k = 0; k < HD; k++) {
        float a = __shfl_sync(0xffffffffu, r[k & 7], (g << 2) | (k >> 3));
        unsigned long long a2 = pack2(a, a);
        ulonglong2 w0 = Wq[k * 8 + c * 2];
        ulonglong2 w1 = Wq[k * 8 + c * 2 + 1];
        o2[0] = fma2_(a2, w0.x, o2[0]);
        o2[1] = fma2_(a2, w0.y, o2[1]);
        o2[2] = fma2_(a2, w1.x, o2[2]);
        o2[3] = fma2_(a2, w1.y, o2[3]);
    }
    if (valid) {
        float v0, v1, v2, v3, v4, v5, v6, v7;
        unpack2(o2[0], v0, v1);
        unpack2(o2[1], v2, v3);
        unpack2(o2[2], v4, v5);
        unpack2(o2[3], v6, v7);
        int4 pv;
        __half2* ph = (__half2*)&pv;
        ph[0] = __floats2half2_rn(v0 * di, v1 * di);
        ph[1] = __floats2half2_rn(v2 * di, v3 * di);
        ph[2] = __floats2half2_rn(v4 * di, v5 * di);
        ph[3] = __floats2half2_rn(v6 * di, v7 * di);
        hout4[node * 4 + c] = pv;
    }
}

// ---------------- fused final: aggregate -> bias -> relu -> sum pool --------
template <bool IN_A>
__global__ void agg_pool_kernel(const float* __restrict__ bias, int n) {
    __shared__ float sh[32 * 32];
    int tid  = threadIdx.x;
    int lane = tid & 31;
    int wid  = tid >> 5;
    int g    = lane >> 2;
    int c    = lane & 3;
    int warp = (blockIdx.x * 1024 + tid) >> 5;
    int node = warp * 8 + g;
    bool valid = node < n;
    int nd = valid ? node : n - 1;
    const int4* __restrict__ hin4 = (const int4*)(IN_A ? g_hA : g_hB);
    float di = g_dinv[nd];
    float acc[8] = {0, 0, 0, 0, 0, 0, 0, 0};
    acc_add8(acc, hin4[nd * 4 + c]);                     // self loop
    int s   = g_row[nd];
    int deg = valid ? (g_row[nd + 1] - s) : 0;
    int mmax = deg;
    mmax = max(mmax, __shfl_xor_sync(0xffffffffu, mmax, 4));
    mmax = max(mmax, __shfl_xor_sync(0xffffffffu, mmax, 8));
    mmax = max(mmax, __shfl_xor_sync(0xffffffffu, mmax, 16));
    int cs = (c < deg) ? g_csrc[s + c] : 0;
    for (int i = 0; i < mmax; i += 4) {
        int csn = (i + 4 + c < deg) ? g_csrc[s + i + 4 + c] : 0;
#pragma unroll
        for (int j = 0; j < 4; j++) {
            int srcj = __shfl_sync(0xffffffffu, cs, (g << 2) | j);
            if (i + j < deg)
                acc_add8(acc, hin4[srcj * 4 + c]);
        }
        cs = csn;
    }
    float4 b0 = ((const float4*)bias)[c * 2];
    float4 b1 = ((const float4*)bias)[c * 2 + 1];
    float r[8];
    r[0] = fmaxf(fmaf(acc[0], di, b0.x), 0.0f);
    r[1] = fmaxf(fmaf(acc[1], di, b0.y), 0.0f);
    r[2] = fmaxf(fmaf(acc[2], di, b0.z), 0.0f);
    r[3] = fmaxf(fmaf(acc[3], di, b0.w), 0.0f);
    r[4] = fmaxf(fmaf(acc[4], di, b1.x), 0.0f);
    r[5] = fmaxf(fmaf(acc[5], di, b1.y), 0.0f);
    r[6] = fmaxf(fmaf(acc[6], di, b1.z), 0.0f);
    r[7] = fmaxf(fmaf(acc[7], di, b1.w), 0.0f);
    if (!valid) {
#pragma unroll
        for (int kk = 0; kk < 8; kk++) r[kk] = 0.0f;
    }
#pragma unroll
    for (int kk = 0; kk < 8; kk++) {
        r[kk] += __shfl_xor_sync(0xffffffffu, r[kk], 4);
        r[kk] += __shfl_xor_sync(0xffffffffu, r[kk], 8);
        r[kk] += __shfl_xor_sync(0xffffffffu, r[kk], 16);
    }
    if (lane < 4) {
#pragma unroll
        for (int kk = 0; kk < 8; kk++)
            sh[wid * 32 + c * 8 + kk] = r[kk];
    }
    __syncthreads();
    if (wid == 0) {
        float s2 = 0.0f;
#pragma unroll
        for (int j = 0; j < 32; j++) s2 += sh[j * 32 + lane];
        atomicAdd(&g_pool[lane], s2);
    }
}

// ---------------- tiny MLP head ---------------------------------------------
__global__ void mlp_kernel(const float* __restrict__ Wl1, const float* __restrict__ bl1,
                           const float* __restrict__ Wl2, const float* __restrict__ bl2,
                           float* __restrict__ out) {
    __shared__ float z[16];
    int t = threadIdx.x;
    if (t < 16) {
        float s = bl1[t];
#pragma unroll
        for (int k = 0; k < 32; k++) s = fmaf(g_pool[k], Wl1[k * 16 + t], s);
        z[t] = fmaxf(s, 0.0f);
    }
    __syncthreads();
    if (t < 3) {
        float s = bl2[t];
#pragma unroll
        for (int j = 0; j < 16; j++) s = fmaf(z[j], Wl2[j * 3 + t], s);
        out[t] = s;
    }
}

// ---------------- launch -----------------------------------------------------
extern "C" void kernel_launch(void* const* d_in, const int* in_sizes, int n_in,
                              void* d_out, int out_size) {
    const float* x   = (const float*)d_in[0];
    const int*   ei  = (const int*)d_in[1];   // int32 (JAX x64 disabled)
    const float* W1  = (const float*)d_in[2];
    const float* b1  = (const float*)d_in[3];
    const float* W2  = (const float*)d_in[4];
    const float* b2  = (const float*)d_in[5];
    const float* W3  = (const float*)d_in[6];
    const float* b3  = (const float*)d_in[7];
    const float* W4  = (const float*)d_in[8];
    const float* b4  = (const float*)d_in[9];
    const float* Wl1 = (const float*)d_in[10];
    const float* bl1 = (const float*)d_in[11];
    const float* Wl2 = (const float*)d_in[12];
    const float* bl2 = (const float*)d_in[13];
    float*       out = (float*)d_out;

    const int fin = in_sizes[2] / HD;       // 61
    const int n   = in_sizes[0] / fin;      // 150000
    const int e   = in_sizes[1] / 2;        // 2400000

    const int T = 256;
    int nB = (n + T - 1) / T;
    int eB = (e + T - 1) / T;
    int nwarps4 = (n + 3) / 4;                            // gemm1: 4 nodes/warp
    int gB = (int)(((long long)nwarps4 * 32 + T - 1) / T);
    int nwarps8 = (n + 7) / 8;                            // agg: 8 nodes/warp
    int aB = (int)(((long long)nwarps8 * 32 + T - 1) / T);
    int pB = (int)(((long long)nwarps8 * 32 + 1023) / 1024);
    int sB = (n + 1023) / 1024;

    // --- graph structure (once per launch) ---
    zero_kernel<<<nB, T>>>(n);
    hist_kernel<<<eB, T>>>(ei, e, n);
    scan1_kernel<<<sB, 1024>>>(n);
    scan2_kernel<<<1, 32>>>(sB);
    scan3_dinv_kernel<<<nB, T>>>(n);
    scatter_kernel<<<eB, T>>>(ei, e, n);

    // --- layers (fused agg+gemm; ping-pong A/B) ---
    gemm1_kernel<<<gB, T>>>(x, W1, n);                 // x@W1*dinv -> A
    agg_gemm_kernel<true><<<aB, T>>>(b1, W2, n);       // agg(A)+b1,relu,@W2*dinv -> B
    agg_gemm_kernel<false><<<aB, T>>>(b2, W3, n);      // agg(B)+b2,relu,@W3*dinv -> A
    agg_gemm_kernel<true><<<aB, T>>>(b3, W4, n);       // agg(A)+b3,relu,@W4*dinv -> B
    agg_pool_kernel<false><<<pB, 1024>>>(b4, n);       // agg(B)+b4,relu -> pool

    // --- MLP head ---
    mlp_kernel<<<1, 32>>>(Wl1, bl1, Wl2, bl2, out);
}

// round 8
// speedup vs baseline: 2.0616x; 1.0356x over previous
#include <cuda_runtime.h>
#include <cuda_fp16.h>

// Problem constants (fixed by the dataset)
constexpr int NMAX = 150000;
constexpr int EMAX = 2400000;
constexpr int HD   = 32;   // hidden dim

// ---------------- scratch (device globals; no allocation allowed) ----------
__device__ __half g_hA[(long long)NMAX * HD];  // ping feature buffer (h * dinv, fp16)
__device__ __half g_hB[(long long)NMAX * HD];  // pong feature buffer
__device__ int    g_cnt[NMAX];                 // degree histogram / fill counters
__device__ int    g_row[NMAX + 1];             // CSR row offsets
__device__ int    g_bsum[1024];                // scan block sums
__device__ float  g_dinv[NMAX];                // 1/sqrt(deg)
__device__ int    g_csrc[EMAX];                // CSR src ids
__device__ float  g_pool[HD];                  // sum-pool result
__device__ int    g_done;                      // pool completion ticket

// ---------------- f32x2 packed math helpers ---------------------------------
__device__ __forceinline__ unsigned long long pack2(float x, float y) {
    unsigned long long r;
    asm("mov.b64 %0, {%1, %2};" : "=l"(r) : "f"(x), "f"(y));
    return r;
}
__device__ __forceinline__ void unpack2(unsigned long long v, float& x, float& y) {
    asm("mov.b64 {%0, %1}, %2;" : "=f"(x), "=f"(y) : "l"(v));
}
__device__ __forceinline__ unsigned long long fma2_(unsigned long long a,
                                                    unsigned long long b,
                                                    unsigned long long c) {
    unsigned long long d;
    asm("fma.rn.f32x2 %0, %1, %2, %3;" : "=l"(d) : "l"(a), "l"(b), "l"(c));
    return d;
}

// ---------------- setup kernels --------------------------------------------
__global__ void zero_kernel(int n) {
    int i = blockIdx.x * blockDim.x + threadIdx.x;
    if (i < n) g_cnt[i] = 0;
    if (i < HD) g_pool[i] = 0.0f;
    if (i == 0) g_done = 0;
}

// edge_index is int32: ei[0:E]=src, ei[E:2E]=dst
__global__ void hist_kernel(const int* __restrict__ ei, int E, int n) {
    int e = blockIdx.x * blockDim.x + threadIdx.x;
    if (e >= E) return;
    unsigned d = (unsigned)ei[E + e];
    if (d < (unsigned)n) atomicAdd(&g_cnt[d], 1);
}

// block-local inclusive scan (1024/block) -> g_row[i+1], block totals -> g_bsum
__global__ void scan1_kernel(int n) {
    __shared__ int sh[1024];
    int i = blockIdx.x * 1024 + threadIdx.x;
    sh[threadIdx.x] = (i < n) ? g_cnt[i] : 0;
    __syncthreads();
    for (int off = 1; off < 1024; off <<= 1) {
        int v = (threadIdx.x >= off) ? sh[threadIdx.x - off] : 0;
        __syncthreads();
        sh[threadIdx.x] += v;
        __syncthreads();
    }
    if (i < n) g_row[i + 1] = sh[threadIdx.x];
    if (threadIdx.x == 1023) g_bsum[blockIdx.x] = sh[1023];
}

// finalize row offsets (+cross-block prefix computed in-block) + dinv + reset
__global__ void scan3_dinv_kernel(int n, int nb) {
    __shared__ int spre[1024];            // exclusive prefix of g_bsum
    int lane = threadIdx.x & 31;
    if (threadIdx.x < 32) {               // warp 0 scans the <=1024 block sums
        int run = 0;
        for (int base = 0; base < nb; base += 32) {
            int v = (base + lane < nb) ? g_bsum[base + lane] : 0;
            int x = v;
#pragma unroll
            for (int off = 1; off < 32; off <<= 1) {
                int y = __shfl_up_sync(0xffffffffu, x, off);
                if (lane >= off) x += y;
            }
            if (base + lane < nb) spre[base + lane] = run + x - v;
            run += __shfl_sync(0xffffffffu, x, 31);
        }
    }
    __syncthreads();
    int i = blockIdx.x * blockDim.x + threadIdx.x;
    if (i < n) {
        g_row[i + 1] += spre[i >> 10];
        g_dinv[i] = rsqrtf((float)(g_cnt[i] + 1));
        g_cnt[i] = 0;
    }
    if (i == 0) g_row[0] = 0;
}

// CSR fill: only src ids (norm is folded into stored features)
__global__ void scatter_kernel(const int* __restrict__ ei, int E, int n) {
    int e = blockIdx.x * blockDim.x + threadIdx.x;
    if (e >= E) return;
    unsigned s = (unsigned)ei[e];
    unsigned d = (unsigned)ei[E + e];
    if (s >= (unsigned)n || d >= (unsigned)n) return;
    int slot = g_row[d] + atomicAdd(&g_cnt[d], 1);
    g_csrc[slot] = (int)s;
}

// ---------------- layer 1: g_hA = (x @ W1) * dinv, fp16 out -----------------
// FOUR nodes per warp: g = lane>>3, fl = lane&7; lane owns 4 outputs (2 f32x2).
__global__ void gemm1_kernel(const float* __restrict__ x,
                             const float* __restrict__ W, int n) {
    __shared__ ulonglong2 Wq[61 * 8];   // Wq[k*8+q] = W[k][4q..4q+3] as 2xf32x2
    for (int i = threadIdx.x; i < 61 * 8; i += blockDim.x) {
        float4 f = ((const float4*)W)[i];
        ulonglong2 u;
        u.x = pack2(f.x, f.y);
        u.y = pack2(f.z, f.w);
        Wq[i] = u;
    }
    __syncthreads();
    int warp = (blockIdx.x * blockDim.x + threadIdx.x) >> 5;
    int lane = threadIdx.x & 31;
    int g    = lane >> 3;
    int fl   = lane & 7;
    int node = warp * 4 + g;
    if (warp * 4 >= n) return;
    bool valid = node < n;
    int nd = valid ? node : n - 1;
    const float* xr = x + (long long)nd * 61;
    float xa[8];
#pragma unroll
    for (int j = 0; j < 8; j++) {
        int idx = fl * 8 + j;
        xa[j] = (idx < 61) ? xr[idx] : 0.0f;
    }
    unsigned long long o0 = 0ULL, o1 = 0ULL;
#pragma unroll
    for (int k = 0; k < 61; k++) {
        float a = __shfl_sync(0xffffffffu, xa[k & 7], (g << 3) | (k >> 3));
        unsigned long long a2 = pack2(a, a);
        ulonglong2 w = Wq[k * 8 + fl];
        o0 = fma2_(a2, w.x, o0);
        o1 = fma2_(a2, w.y, o1);
    }
    if (valid) {
        float di = g_dinv[node];
        float v0, v1, v2, v3;
        unpack2(o0, v0, v1);
        unpack2(o1, v2, v3);
        __half2 h0 = __floats2half2_rn(v0 * di, v1 * di);
        __half2 h1 = __floats2half2_rn(v2 * di, v3 * di);
        uint2 pv;
        pv.x = *(unsigned*)&h0;
        pv.y = *(unsigned*)&h1;
        *(uint2*)&g_hA[node * HD + 4 * fl] = pv;
    }
}

// ---------------- agg helpers ------------------------------------------------
// self-loop: full fp32 add of one int4 (8 fp16)
__device__ __forceinline__ void acc_add8(float* acc, int4 v) {
    const __half2* h = (const __half2*)&v;
#pragma unroll
    for (int q = 0; q < 4; q++) {
        float2 f = __half22float2(h[q]);
        acc[2 * q] += f.x; acc[2 * q + 1] += f.y;
    }
}
// 4-edge group: tree-sum in fp16 (12 HADD2), single convert+add to fp32
__device__ __forceinline__ void acc_add4x8(float* acc, int4 v0, int4 v1,
                                           int4 v2, int4 v3) {
    const __half2* a = (const __half2*)&v0;
    const __half2* b = (const __half2*)&v1;
    const __half2* c = (const __half2*)&v2;
    const __half2* d = (const __half2*)&v3;
#pragma unroll
    for (int q = 0; q < 4; q++) {
        __half2 s = __hadd2(__hadd2(a[q], b[q]), __hadd2(c[q], d[q]));
        float2 f = __half22float2(s);
        acc[2 * q] += f.x; acc[2 * q + 1] += f.y;
    }
}

// ---------------- fused: aggregate -> bias -> relu -> next GEMM -> *dinv ----
// EIGHT nodes per warp: group g = lane>>2, chunk c = lane&3.
// Lane owns 8 features [c*8..c*8+7]. csrc prefetched one iteration ahead.
template <bool IN_A>
__global__ void agg_gemm_kernel(const float* __restrict__ bias,
                                const float* __restrict__ Wn, int n) {
    __shared__ ulonglong2 Wq[HD * 8];
    for (int i = threadIdx.x; i < HD * 8; i += blockDim.x) {
        float4 f = ((const float4*)Wn)[i];
        ulonglong2 u;
        u.x = pack2(f.x, f.y);
        u.y = pack2(f.z, f.w);
        Wq[i] = u;
    }
    __syncthreads();
    int warp = (blockIdx.x * blockDim.x + threadIdx.x) >> 5;
    int lane = threadIdx.x & 31;
    int g    = lane >> 2;
    int c    = lane & 3;
    int node = warp * 8 + g;
    if (warp * 8 >= n) return;
    bool valid = node < n;
    int nd = valid ? node : n - 1;
    const int4* __restrict__ hin4 = (const int4*)(IN_A ? g_hA : g_hB);
    int4* __restrict__ hout4      = (int4*)(IN_A ? g_hB : g_hA);
    float di = g_dinv[nd];
    float acc[8] = {0, 0, 0, 0, 0, 0, 0, 0};
    acc_add8(acc, hin4[nd * 4 + c]);                     // self loop
    int s   = g_row[nd];
    int deg = valid ? (g_row[nd + 1] - s) : 0;
    int mmax = deg;
    mmax = max(mmax, __shfl_xor_sync(0xffffffffu, mmax, 4));
    mmax = max(mmax, __shfl_xor_sync(0xffffffffu, mmax, 8));
    mmax = max(mmax, __shfl_xor_sync(0xffffffffu, mmax, 16));
    const int4 zero4 = make_int4(0, 0, 0, 0);
    int cs = (c < deg) ? g_csrc[s + c] : 0;              // prefetch i=0
    for (int i = 0; i < mmax; i += 4) {
        int csn = (i + 4 + c < deg) ? g_csrc[s + i + 4 + c] : 0;
        int s0 = __shfl_sync(0xffffffffu, cs, (g << 2) | 0);
        int s1 = __shfl_sync(0xffffffffu, cs, (g << 2) | 1);
        int s2 = __shfl_sync(0xffffffffu, cs, (g << 2) | 2);
        int s3 = __shfl_sync(0xffffffffu, cs, (g << 2) | 3);
        int4 v0 = (i + 0 < deg) ? hin4[s0 * 4 + c] : zero4;
        int4 v1 = (i + 1 < deg) ? hin4[s1 * 4 + c] : zero4;
        int4 v2 = (i + 2 < deg) ? hin4[s2 * 4 + c] : zero4;
        int4 v3 = (i + 3 < deg) ? hin4[s3 * 4 + c] : zero4;
        acc_add4x8(acc, v0, v1, v2, v3);
        cs = csn;
    }
    float4 b0 = ((const float4*)bias)[c * 2];
    float4 b1 = ((const float4*)bias)[c * 2 + 1];
    float r[8];
    r[0] = fmaxf(fmaf(acc[0], di, b0.x), 0.0f);
    r[1] = fmaxf(fmaf(acc[1], di, b0.y), 0.0f);
    r[2] = fmaxf(fmaf(acc[2], di, b0.z), 0.0f);
    r[3] = fmaxf(fmaf(acc[3], di, b0.w), 0.0f);
    r[4] = fmaxf(fmaf(acc[4], di, b1.x), 0.0f);
    r[5] = fmaxf(fmaf(acc[5], di, b1.y), 0.0f);
    r[6] = fmaxf(fmaf(acc[6], di, b1.z), 0.0f);
    r[7] = fmaxf(fmaf(acc[7], di, b1.w), 0.0f);
    unsigned long long o2[4] = {0ULL, 0ULL, 0ULL, 0ULL};
#pragma unroll
    for (int k = 0; k < HD; k++) {
        float a = __shfl_sync(0xffffffffu, r[k & 7], (g << 2) | (k >> 3));
        unsigned long long a2 = pack2(a, a);
        ulonglong2 w0 = Wq[k * 8 + c * 2];
        ulonglong2 w1 = Wq[k * 8 + c * 2 + 1];
        o2[0] = fma2_(a2, w0.x, o2[0]);
        o2[1] = fma2_(a2, w0.y, o2[1]);
        o2[2] = fma2_(a2, w1.x, o2[2]);
        o2[3] = fma2_(a2, w1.y, o2[3]);
    }
    if (valid) {
        float v0, v1, v2, v3, v4, v5, v6, v7;
        unpack2(o2[0], v0, v1);
        unpack2(o2[1], v2, v3);
        unpack2(o2[2], v4, v5);
        unpack2(o2[3], v6, v7);
        int4 pv;
        __half2* ph = (__half2*)&pv;
        ph[0] = __floats2half2_rn(v0 * di, v1 * di);
        ph[1] = __floats2half2_rn(v2 * di, v3 * di);
        ph[2] = __floats2half2_rn(v4 * di, v5 * di);
        ph[3] = __floats2half2_rn(v6 * di, v7 * di);
        hout4[node * 4 + c] = pv;
    }
}

// ---------------- fused final: agg -> bias -> relu -> pool -> MLP head ------
// Last block (threadfence+ticket) computes the 32->16->3 MLP and writes out.
template <bool IN_A>
__global__ void agg_pool_mlp_kernel(const float* __restrict__ bias, int n,
                                    const float* __restrict__ Wl1,
                                    const float* __restrict__ bl1,
                                    const float* __restrict__ Wl2,
                                    const float* __restrict__ bl2,
                                    float* __restrict__ out) {
    __shared__ float sh[32 * 32];
    __shared__ int sh_last;
    int tid  = threadIdx.x;
    int lane = tid & 31;
    int wid  = tid >> 5;
    int g    = lane >> 2;
    int c    = lane & 3;
    int warp = (blockIdx.x * 1024 + tid) >> 5;
    int node = warp * 8 + g;
    bool valid = node < n;
    int nd = valid ? node : n - 1;
    const int4* __restrict__ hin4 = (const int4*)(IN_A ? g_hA : g_hB);
    float di = g_dinv[nd];
    float acc[8] = {0, 0, 0, 0, 0, 0, 0, 0};
    acc_add8(acc, hin4[nd * 4 + c]);                     // self loop
    int s   = g_row[nd];
    int deg = valid ? (g_row[nd + 1] - s) : 0;
    int mmax = deg;
    mmax = max(mmax, __shfl_xor_sync(0xffffffffu, mmax, 4));
    mmax = max(mmax, __shfl_xor_sync(0xffffffffu, mmax, 8));
    mmax = max(mmax, __shfl_xor_sync(0xffffffffu, mmax, 16));
    const int4 zero4 = make_int4(0, 0, 0, 0);
    int cs = (c < deg) ? g_csrc[s + c] : 0;
    for (int i = 0; i < mmax; i += 4) {
        int csn = (i + 4 + c < deg) ? g_csrc[s + i + 4 + c] : 0;
        int s0 = __shfl_sync(0xffffffffu, cs, (g << 2) | 0);
        int s1 = __shfl_sync(0xffffffffu, cs, (g << 2) | 1);
        int s2 = __shfl_sync(0xffffffffu, cs, (g << 2) | 2);
        int s3 = __shfl_sync(0xffffffffu, cs, (g << 2) | 3);
        int4 v0 = (i + 0 < deg) ? hin4[s0 * 4 + c] : zero4;
        int4 v1 = (i + 1 < deg) ? hin4[s1 * 4 + c] : zero4;
        int4 v2 = (i + 2 < deg) ? hin4[s2 * 4 + c] : zero4;
        int4 v3 = (i + 3 < deg) ? hin4[s3 * 4 + c] : zero4;
        acc_add4x8(acc, v0, v1, v2, v3);
        cs = csn;
    }
    float4 b0 = ((const float4*)bias)[c * 2];
    float4 b1 = ((const float4*)bias)[c * 2 + 1];
    float r[8];
    r[0] = fmaxf(fmaf(acc[0], di, b0.x), 0.0f);
    r[1] = fmaxf(fmaf(acc[1], di, b0.y), 0.0f);
    r[2] = fmaxf(fmaf(acc[2], di, b0.z), 0.0f);
    r[3] = fmaxf(fmaf(acc[3], di, b0.w), 0.0f);
    r[4] = fmaxf(fmaf(acc[4], di, b1.x), 0.0f);
    r[5] = fmaxf(fmaf(acc[5], di, b1.y), 0.0f);
    r[6] = fmaxf(fmaf(acc[6], di, b1.z), 0.0f);
    r[7] = fmaxf(fmaf(acc[7], di, b1.w), 0.0f);
    if (!valid) {
#pragma unroll
        for (int kk = 0; kk < 8; kk++) r[kk] = 0.0f;
    }
#pragma unroll
    for (int kk = 0; kk < 8; kk++) {
        r[kk] += __shfl_xor_sync(0xffffffffu, r[kk], 4);
        r[kk] += __shfl_xor_sync(0xffffffffu, r[kk], 8);
        r[kk] += __shfl_xor_sync(0xffffffffu, r[kk], 16);
    }
    if (lane < 4) {
#pragma unroll
        for (int kk = 0; kk < 8; kk++)
            sh[wid * 32 + c * 8 + kk] = r[kk];
    }
    __syncthreads();
    if (wid == 0) {
        float s2 = 0.0f;
#pragma unroll
        for (int j = 0; j < 32; j++) s2 += sh[j * 32 + lane];
        atomicAdd(&g_pool[lane], s2);
        __threadfence();
    }
    __syncthreads();
    if (tid == 0) {
        int t = atomicAdd(&g_done, 1);
        sh_last = (t == (int)gridDim.x - 1);
    }
    __syncthreads();
    if (sh_last && wid == 0) {
        // last block: read final pool (atomic read-through) and run MLP head
        float pv = atomicAdd(&g_pool[lane], 0.0f);
        sh[lane] = pv;
        __syncwarp();
        float z = 0.0f;
        if (lane < 16) {
            float sacc = bl1[lane];
#pragma unroll
            for (int k = 0; k < 32; k++)
                sacc = fmaf(sh[k], Wl1[k * 16 + lane], sacc);
            z = fmaxf(sacc, 0.0f);
            sh[32 + lane] = z;
        }
        __syncwarp();
        if (lane < 3) {
            float sacc = bl2[lane];
#pragma unroll
            for (int j = 0; j < 16; j++)
                sacc = fmaf(sh[32 + j], Wl2[j * 3 + lane], sacc);
            out[lane] = sacc;
        }
    }
}

// ---------------- launch -----------------------------------------------------
extern "C" void kernel_launch(void* const* d_in, const int* in_sizes, int n_in,
                              void* d_out, int out_size) {
    const float* x   = (const float*)d_in[0];
    const int*   ei  = (const int*)d_in[1];   // int32 (JAX x64 disabled)
    const float* W1  = (const float*)d_in[2];
    const float* b1  = (const float*)d_in[3];
    const float* W2  = (const float*)d_in[4];
    const float* b2  = (const float*)d_in[5];
    const float* W3  = (const float*)d_in[6];
    const float* b3  = (const float*)d_in[7];
    const float* W4  = (const float*)d_in[8];
    const float* b4  = (const float*)d_in[9];
    const float* Wl1 = (const float*)d_in[10];
    const float* bl1 = (const float*)d_in[11];
    const float* Wl2 = (const float*)d_in[12];
    const float* bl2 = (const float*)d_in[13];
    float*       out = (float*)d_out;

    const int fin = in_sizes[2] / HD;       // 61
    const int n   = in_sizes[0] / fin;      // 150000
    const int e   = in_sizes[1] / 2;        // 2400000

    const int T = 256;
    int nB = (n + T - 1) / T;
    int eB = (e + T - 1) / T;
    int nwarps4 = (n + 3) / 4;                            // gemm1: 4 nodes/warp
    int gB = (int)(((long long)nwarps4 * 32 + T - 1) / T);
    int nwarps8 = (n + 7) / 8;                            // agg: 8 nodes/warp
    int aB = (int)(((long long)nwarps8 * 32 + T - 1) / T);
    int pB = (int)(((long long)nwarps8 * 32 + 1023) / 1024);
    int sB = (n + 1023) / 1024;

    // --- graph structure (once per launch) ---
    zero_kernel<<<nB, T>>>(n);
    hist_kernel<<<eB, T>>>(ei, e, n);
    scan1_kernel<<<sB, 1024>>>(n);
    scan3_dinv_kernel<<<nB, T>>>(n, sB);
    scatter_kernel<<<eB, T>>>(ei, e, n);

    // --- layers (fused agg+gemm; ping-pong A/B) ---
    gemm1_kernel<<<gB, T>>>(x, W1, n);                 // x@W1*dinv -> A
    agg_gemm_kernel<true><<<aB, T>>>(b1, W2, n);       // agg(A)->B
    agg_gemm_kernel<false><<<aB, T>>>(b2, W3, n);      // agg(B)->A
    agg_gemm_kernel<true><<<aB, T>>>(b3, W4, n);       // agg(A)->B
    agg_pool_mlp_kernel<false><<<pB, 1024>>>(b4, n, Wl1, bl1, Wl2, bl2, out);
}